// round 1
// baseline (speedup 1.0000x reference)
#include <cuda_runtime.h>

#define DIM 496

// pair index of (x,y), x<y, in itertools.combinations(range(32),2) order
__device__ __forceinline__ int pidx(int x, int y) {
    return x * 31 - ((x * (x - 1)) >> 1) + (y - x - 1);
}

// Decode orbit o in [0,124): 4 member basis indices m[0..3] laid out as
// m[alpha*2+beta], outer gate gO acting on alpha, inner gate gI on beta.
// Gate id 15 == identity (cos=1, sin=0).
__device__ __forceinline__ void decode_orbit(int o, int m[4], int& gO, int& gI) {
    if (o < 105) {                       // cross-block (g<h<15): R_g (x) R_h
        int g = 0, rem = o;
        while (rem >= 14 - g) { rem -= 14 - g; ++g; }
        int h = g + 1 + rem;
        gO = g; gI = h;
        m[0] = pidx(2 * g,     2 * h);
        m[1] = pidx(2 * g,     2 * h + 1);
        m[2] = pidx(2 * g + 1, 2 * h);
        m[3] = pidx(2 * g + 1, 2 * h + 1);
    } else if (o < 120) {                // block g paired with qubits 30/31: R_g (x) I
        int g = o - 105;
        gO = g; gI = 15;
        m[0] = pidx(2 * g,     30);
        m[1] = pidx(2 * g,     31);
        m[2] = pidx(2 * g + 1, 30);
        m[3] = pidx(2 * g + 1, 31);
    } else {                             // 16 identity singletons grouped 4-at-a-time
        int j = o - 120;
        gO = 15; gI = 15;
#pragma unroll
        for (int k = 0; k < 4; ++k) {
            int q = 4 * j + k;
            m[k] = pidx(2 * q, 2 * q + 1);
        }
    }
}

__global__ __launch_bounds__(128) void rbs_density_kernel(
    const float* __restrict__ rho, const float* __restrict__ angles,
    float* __restrict__ out)
{
    __shared__ float S[4][DIM];          // 4 rows of one row-orbit, 7936 B
    __shared__ float cs[16], sn[16];

    const int tid = threadIdx.x;
    const int ro  = blockIdx.x;          // row orbit 0..123
    const int b   = blockIdx.y;          // batch 0..7

    if (tid < 16) {
        if (tid < 15) {
            float s, c;
            sincosf(angles[tid], &s, &c);
            cs[tid] = c; sn[tid] = s;
        } else {
            cs[15] = 1.0f; sn[15] = 0.0f;
        }
    }

    int rm[4], rgO, rgI;
    decode_orbit(ro, rm, rgO, rgI);

    const size_t boff = (size_t)b * DIM * DIM;

    // coalesced float4 load of the 4 rows (496 floats = 124 float4 each)
    if (tid < 124) {
#pragma unroll
        for (int i = 0; i < 4; ++i) {
            const float4 v = ((const float4*)(rho + boff + (size_t)rm[i] * DIM))[tid];
            ((float4*)S[i])[tid] = v;
        }
    }
    __syncthreads();

    // Row transform: M <- U_r * M. Each thread owns a strided set of columns.
    {
        const float ci = cs[rgI], si = sn[rgI];
        const float co = cs[rgO], so = sn[rgO];
        for (int c = tid; c < DIM; c += 128) {
            float v0 = S[0][c], v1 = S[1][c], v2 = S[2][c], v3 = S[3][c];
            // inner rotation R_h on beta: pairs (0,1) and (2,3)
            float t0 = ci * v0 + si * v1, t1 = ci * v1 - si * v0;
            float t2 = ci * v2 + si * v3, t3 = ci * v3 - si * v2;
            // outer rotation R_g on alpha: pairs (0,2) and (1,3)
            S[0][c] = co * t0 + so * t2;  S[2][c] = co * t2 - so * t0;
            S[1][c] = co * t1 + so * t3;  S[3][c] = co * t3 - so * t1;
        }
    }
    __syncthreads();

    // Column transform: M <- M * U_c^T. Thread t owns column-orbit t
    // (disjoint 4-column sets -> in-place safe).
    if (tid < 124) {
        int cm[4], cgO, cgI;
        decode_orbit(tid, cm, cgO, cgI);
        const float ci = cs[cgI], si = sn[cgI];
        const float co = cs[cgO], so = sn[cgO];
#pragma unroll
        for (int i = 0; i < 4; ++i) {
            float w0 = S[i][cm[0]], w1 = S[i][cm[1]];
            float w2 = S[i][cm[2]], w3 = S[i][cm[3]];
            float t0 = ci * w0 + si * w1, t1 = ci * w1 - si * w0;
            float t2 = ci * w2 + si * w3, t3 = ci * w3 - si * w2;
            S[i][cm[0]] = co * t0 + so * t2;  S[i][cm[2]] = co * t2 - so * t0;
            S[i][cm[1]] = co * t1 + so * t3;  S[i][cm[3]] = co * t3 - so * t1;
        }
    }
    __syncthreads();

    // coalesced float4 store of the 4 transformed rows
    if (tid < 124) {
#pragma unroll
        for (int i = 0; i < 4; ++i) {
            ((float4*)(out + boff + (size_t)rm[i] * DIM))[tid] =
                ((const float4*)S[i])[tid];
        }
    }
}

extern "C" void kernel_launch(void* const* d_in, const int* in_sizes, int n_in,
                              void* d_out, int out_size) {
    const float* rho = (const float*)d_in[0];
    const float* ang = (const float*)d_in[1];
    // defensive: metadata order should be (input_state, angles); swap if reversed
    if (n_in >= 2 && in_sizes[0] == 15) {
        rho = (const float*)d_in[1];
        ang = (const float*)d_in[0];
    }
    dim3 grid(124, 8);
    rbs_density_kernel<<<grid, 128>>>(rho, ang, (float*)d_out);
}